// round 1
// baseline (speedup 1.0000x reference)
#include <cuda_runtime.h>
#include <cuda_bf16.h>
#include <cstdint>

// EdgeBlock: out = LN( relu( [n[s]; n[r]; e] @ W1 + b1 ) @ W2 + b2 )
// D = 128, HIDDEN = 128, in_dim = 384. All fp32.
//
// One CTA = 128 edges. GEMM1: [128,384]@[384,128] with gathered A staged in
// smem (K chunks of 32) ; GEMM2: [128,128]@[128,128] with W2 staged in smem.
// 256 threads, each owns an 8x8 micro-tile. LayerNorm epilogue via
// half-warp shuffle reductions (row e is spread over the 16 tx lanes).

#define TM 128
#define KC 32
#define AS_STRIDE 36      // 32 + 4 pad, keeps float4 stores aligned & conflict-free
#define WS_STRIDE 132     // 128 + 4 pad
// smem: H1s [128][132] floats, then a 16896-float region shared by
// (As [128][36] + Ws [32][132]) in phase 1 and W2s [128][132] in phase 2.
#define SMEM_FLOATS (128*132 + 16896)
#define SMEM_BYTES  (SMEM_FLOATS * 4)

__global__ __launch_bounds__(256, 1)
void edge_block_kernel(const float* __restrict__ node_attr,
                       const float* __restrict__ edge_attr,
                       const int*   __restrict__ senders,
                       const int*   __restrict__ receivers,
                       const float* __restrict__ W1,
                       const float* __restrict__ b1,
                       const float* __restrict__ W2,
                       const float* __restrict__ b2,
                       const float* __restrict__ ln_gamma,
                       const float* __restrict__ ln_beta,
                       float* __restrict__ out,
                       int E)
{
    extern __shared__ float smem[];
    float* H1s = smem;                      // [128][132]
    float* As  = smem + 128 * 132;          // [128][36]   (phase 1)
    float* Ws  = As + 128 * AS_STRIDE;      // [32][132]   (phase 1)
    float* W2s = smem + 128 * 132;          // [128][132]  (phase 2, aliases As/Ws)

    const int tid = threadIdx.x;
    const int tx  = tid & 15;               // column group (8 cols each)
    const int ty  = tid >> 4;               // row group (8 rows each)
    const int eb  = blockIdx.x * TM;

    // ---- gather identity: 2 threads per edge-row, 16 contiguous floats each
    const int ge = tid >> 1;                // row in tile 0..127
    const int gh = tid & 1;                 // half of the 32-float chunk
    int eg_g = eb + ge;
    if (eg_g >= E) eg_g = E - 1;            // clamp: loads stay valid
    const int sidx = senders[eg_g];
    const int ridx = receivers[eg_g];

    float acc[8][8];
    #pragma unroll
    for (int i = 0; i < 8; ++i)
        #pragma unroll
        for (int j = 0; j < 8; ++j) acc[i][j] = 0.f;

    // =========================== Phase 1: GEMM1, K = 384 in 12 chunks of 32
    for (int chunk = 0; chunk < 12; ++chunk) {
        // gather A chunk: As[e][kk] for kk in [chunk*32, +32)
        const float* src;
        if (chunk < 4)       src = node_attr + (size_t)sidx * 128 + chunk * 32;
        else if (chunk < 8)  src = node_attr + (size_t)ridx * 128 + (chunk - 4) * 32;
        else                 src = edge_attr + (size_t)eg_g * 128 + (chunk - 8) * 32;

        {
            const float4* s4 = reinterpret_cast<const float4*>(src + gh * 16);
            float4 v0 = s4[0], v1 = s4[1], v2 = s4[2], v3 = s4[3];
            float4* d4 = reinterpret_cast<float4*>(As + ge * AS_STRIDE + gh * 16);
            d4[0] = v0; d4[1] = v1; d4[2] = v2; d4[3] = v3;
        }

        // load W1 chunk rows [chunk*32, +32) x 128 cols
        {
            int kk = tid >> 3;
            int q  = tid & 7;
            const float4* wsrc = reinterpret_cast<const float4*>(W1 + (size_t)(chunk * 32 + kk) * 128);
            float4* wdst = reinterpret_cast<float4*>(Ws + kk * WS_STRIDE);
            #pragma unroll
            for (int r = 0; r < 4; ++r) wdst[q + 8 * r] = wsrc[q + 8 * r];
        }
        __syncthreads();

        #pragma unroll 8
        for (int kk = 0; kk < KC; ++kk) {
            float a[8];
            #pragma unroll
            for (int i = 0; i < 8; ++i) a[i] = As[(ty * 8 + i) * AS_STRIDE + kk];
            float4 bv0 = *reinterpret_cast<const float4*>(Ws + kk * WS_STRIDE + tx * 8);
            float4 bv1 = *reinterpret_cast<const float4*>(Ws + kk * WS_STRIDE + tx * 8 + 4);
            float b[8] = {bv0.x, bv0.y, bv0.z, bv0.w, bv1.x, bv1.y, bv1.z, bv1.w};
            #pragma unroll
            for (int i = 0; i < 8; ++i)
                #pragma unroll
                for (int j = 0; j < 8; ++j)
                    acc[i][j] = fmaf(a[i], b[j], acc[i][j]);
        }
        __syncthreads();
    }

    // ---- bias + ReLU, write H1 tile to smem
    {
        float bb[8];
        #pragma unroll
        for (int j = 0; j < 8; ++j) bb[j] = b1[tx * 8 + j];
        #pragma unroll
        for (int i = 0; i < 8; ++i) {
            float hv[8];
            #pragma unroll
            for (int j = 0; j < 8; ++j) {
                float v = acc[i][j] + bb[j];
                hv[j] = v > 0.f ? v : 0.f;
            }
            float4* dst = reinterpret_cast<float4*>(H1s + (ty * 8 + i) * WS_STRIDE + tx * 8);
            dst[0] = make_float4(hv[0], hv[1], hv[2], hv[3]);
            dst[1] = make_float4(hv[4], hv[5], hv[6], hv[7]);
        }
    }
    __syncthreads();   // all Ws reads done + H1 visible before W2s overwrite

    // ---- stage W2 [128][128] into smem (aliases phase-1 scratch)
    {
        #pragma unroll
        for (int r = 0; r < 16; ++r) {
            int f   = tid + 256 * r;        // 0..4095 float4s
            int row = f >> 5;
            int q   = f & 31;
            reinterpret_cast<float4*>(W2s + row * WS_STRIDE)[q] =
                reinterpret_cast<const float4*>(W2 + (size_t)row * 128)[q];
        }
    }
    __syncthreads();

    // =========================== Phase 2: GEMM2, K = 128
    float acc2[8][8];
    #pragma unroll
    for (int i = 0; i < 8; ++i)
        #pragma unroll
        for (int j = 0; j < 8; ++j) acc2[i][j] = 0.f;

    #pragma unroll 8
    for (int kk = 0; kk < 128; ++kk) {
        float a[8];
        #pragma unroll
        for (int i = 0; i < 8; ++i) a[i] = H1s[(ty * 8 + i) * WS_STRIDE + kk];
        float4 bv0 = *reinterpret_cast<const float4*>(W2s + kk * WS_STRIDE + tx * 8);
        float4 bv1 = *reinterpret_cast<const float4*>(W2s + kk * WS_STRIDE + tx * 8 + 4);
        float b[8] = {bv0.x, bv0.y, bv0.z, bv0.w, bv1.x, bv1.y, bv1.z, bv1.w};
        #pragma unroll
        for (int i = 0; i < 8; ++i)
            #pragma unroll
            for (int j = 0; j < 8; ++j)
                acc2[i][j] = fmaf(a[i], b[j], acc2[i][j]);
    }

    // =========================== Epilogue: +b2, LayerNorm per edge row, store
    {
        float b2f[8], gf[8], bf[8];
        #pragma unroll
        for (int j = 0; j < 8; ++j) {
            b2f[j] = b2[tx * 8 + j];
            gf[j]  = ln_gamma[tx * 8 + j];
            bf[j]  = ln_beta[tx * 8 + j];
        }
        const int eg0 = eb + ty * 8;
        #pragma unroll
        for (int i = 0; i < 8; ++i) {
            float v[8];
            float s = 0.f, s2 = 0.f;
            #pragma unroll
            for (int j = 0; j < 8; ++j) {
                v[j] = acc2[i][j] + b2f[j];
                s  += v[j];
                s2 += v[j] * v[j];
            }
            // reduce across the 16 tx lanes (row is contained in a half-warp)
            #pragma unroll
            for (int m = 1; m < 16; m <<= 1) {
                s  += __shfl_xor_sync(0xffffffffu, s,  m);
                s2 += __shfl_xor_sync(0xffffffffu, s2, m);
            }
            float mean = s * (1.f / 128.f);
            float var  = s2 * (1.f / 128.f) - mean * mean;
            float rstd = rsqrtf(var + 1e-5f);
            int eg = eg0 + i;
            if (eg < E) {
                float o[8];
                #pragma unroll
                for (int j = 0; j < 8; ++j)
                    o[j] = (v[j] - mean) * rstd * gf[j] + bf[j];
                float4* dst = reinterpret_cast<float4*>(out + (size_t)eg * 128 + tx * 8);
                dst[0] = make_float4(o[0], o[1], o[2], o[3]);
                dst[1] = make_float4(o[4], o[5], o[6], o[7]);
            }
        }
    }
}

extern "C" void kernel_launch(void* const* d_in, const int* in_sizes, int n_in,
                              void* d_out, int out_size)
{
    (void)n_in; (void)out_size;
    const float* node_attr = (const float*)d_in[0];
    const float* edge_attr = (const float*)d_in[1];
    const int*   senders   = (const int*)  d_in[2];
    const int*   receivers = (const int*)  d_in[3];
    const float* W1        = (const float*)d_in[4];
    const float* b1        = (const float*)d_in[5];
    const float* W2        = (const float*)d_in[6];
    const float* b2        = (const float*)d_in[7];
    const float* ln_gamma  = (const float*)d_in[8];
    const float* ln_beta   = (const float*)d_in[9];
    float* out = (float*)d_out;

    const int E = in_sizes[2];   // senders_idx element count

    cudaFuncSetAttribute(edge_block_kernel,
                         cudaFuncAttributeMaxDynamicSharedMemorySize, SMEM_BYTES);

    const int grid = (E + TM - 1) / TM;
    edge_block_kernel<<<grid, 256, SMEM_BYTES>>>(
        node_attr, edge_attr, senders, receivers,
        W1, b1, W2, b2, ln_gamma, ln_beta, out, E);
}

// round 3
// speedup vs baseline: 1.8948x; 1.8948x over previous
#include <cuda_runtime.h>
#include <cstdint>

// EdgeBlock: out = LN( relu( [n[s]; n[r]; e] @ W1 + b1 ) @ W2 + b2 )
// tf32 warp-level mma.sync (m16n8k8) — works on base sm_103 target.
//
// CTA = 256 edges. 8 warps in a 4(M) x 2(N) grid, warp tile 64x64.
// Operands staged k-major in smem as pre-converted tf32:
//   A_s[k][m]  stride 264   (GEMM1 A chunk, 64 x 256)
//   B_s[k][n]  stride 136   (GEMM1 W1 chunk, 64 x 128)
//   H_s[k][m]  stride 264   (GEMM2 A, 128 x 256; aliases A_s/B_s)
//   W2_s[k][n] stride 136   (GEMM2 B, 128 x 128)
// Strides chosen so fragment reads hit bank (8*tig + g) -> conflict-free.

#define CTA_M   256
#define THREADS 256
#define AS_STR  264
#define BS_STR  136

// smem layout in floats
#define OFF_A   0            // 64*264  = 16896
#define OFF_B   16896        // 64*136  =  8704   (ends 25600)
#define OFF_H   0            // 128*264 = 33792   (phase 2, aliases A/B)
#define OFF_W2  33792        // 128*136 = 17408   (ends 51200)
#define OFF_PRM 51200        // b1,b2,gamma,beta  (512)
#define OFF_PS  51712        // LN partials: sums[2][256], sqs[2][256] (1024)
#define SMEM_FLOATS 52736
#define SMEM_BYTES  (SMEM_FLOATS * 4)

__device__ __forceinline__ uint32_t f2tf(float f) {
    uint32_t u;
    asm("cvt.rna.tf32.f32 %0, %1;" : "=r"(u) : "f"(f));
    return u;
}

__device__ __forceinline__ void mma8(float* d,
                                     uint32_t a0, uint32_t a1, uint32_t a2, uint32_t a3,
                                     uint32_t b0, uint32_t b1) {
    asm volatile(
        "mma.sync.aligned.m16n8k8.row.col.f32.tf32.tf32.f32 "
        "{%0,%1,%2,%3}, {%4,%5,%6,%7}, {%8,%9}, {%0,%1,%2,%3};"
        : "+f"(d[0]), "+f"(d[1]), "+f"(d[2]), "+f"(d[3])
        : "r"(a0), "r"(a1), "r"(a2), "r"(a3), "r"(b0), "r"(b1));
}

__global__ __launch_bounds__(THREADS, 1)
void edge_block_mma(const float* __restrict__ node_attr,
                    const float* __restrict__ edge_attr,
                    const int*   __restrict__ senders,
                    const int*   __restrict__ receivers,
                    const float* __restrict__ W1,
                    const float* __restrict__ b1,
                    const float* __restrict__ W2,
                    const float* __restrict__ b2,
                    const float* __restrict__ ln_g,
                    const float* __restrict__ ln_b,
                    float* __restrict__ out,
                    int E)
{
    extern __shared__ float smem[];
    uint32_t* Asu = reinterpret_cast<uint32_t*>(smem + OFF_A);
    uint32_t* Bsu = reinterpret_cast<uint32_t*>(smem + OFF_B);
    uint32_t* Hsu = reinterpret_cast<uint32_t*>(smem + OFF_H);
    uint32_t* W2u = reinterpret_cast<uint32_t*>(smem + OFF_W2);
    float*    prm = smem + OFF_PRM;
    float*    ps  = smem + OFF_PS;

    const int tid  = threadIdx.x;
    const int lane = tid & 31;
    const int wid  = tid >> 5;
    const int g    = lane >> 2;        // group id (row within fragment)
    const int tig  = lane & 3;         // thread-in-group (k / col select)
    const int wm   = (wid >> 1) * 64;  // warp M offset
    const int wn   = (wid & 1) * 64;   // warp N offset
    const int wc   = wid & 1;          // warp column
    const int eb   = blockIdx.x * CTA_M;

    if (tid < 128) {
        prm[tid]       = b1[tid];
        prm[128 + tid] = b2[tid];
        prm[256 + tid] = ln_g[tid];
        prm[384 + tid] = ln_b[tid];
    }

    int eg = eb + tid;
    if (eg >= E) eg = E - 1;
    const int sidx = senders[eg];
    const int ridx = receivers[eg];

    // ---- stage W2 (tf32, k-major [128][136]) once; region is disjoint
    {
        const int row  = tid >> 1;
        const int half = tid & 1;
        const float4* s4 = reinterpret_cast<const float4*>(W2 + (size_t)row * 128 + half * 64);
        uint4* d4 = reinterpret_cast<uint4*>(W2u + row * BS_STR + half * 64);
        #pragma unroll
        for (int r = 0; r < 16; ++r) {
            float4 v = s4[r];
            d4[r] = make_uint4(f2tf(v.x), f2tf(v.y), f2tf(v.z), f2tf(v.w));
        }
    }

    float acc[4][8][4];
    #pragma unroll
    for (int i = 0; i < 4; ++i)
        #pragma unroll
        for (int j = 0; j < 8; ++j)
            #pragma unroll
            for (int c = 0; c < 4; ++c) acc[i][j][c] = 0.f;

    // ======================= GEMM1: K = 384, 6 chunks of 64 =======================
    #pragma unroll 1
    for (int ch = 0; ch < 6; ++ch) {
        const float* src = (ch < 2) ? node_attr + (size_t)sidx * 128 + ch * 64
                         : (ch < 4) ? node_attr + (size_t)ridx * 128 + (ch - 2) * 64
                                    : edge_attr + (size_t)eg  * 128 + (ch - 4) * 64;
        // gather: thread-per-row, 256B contiguous, transpose-store k-major
        #pragma unroll
        for (int q = 0; q < 16; ++q) {
            float4 v = reinterpret_cast<const float4*>(src)[q];
            Asu[(4 * q + 0) * AS_STR + tid] = f2tf(v.x);
            Asu[(4 * q + 1) * AS_STR + tid] = f2tf(v.y);
            Asu[(4 * q + 2) * AS_STR + tid] = f2tf(v.z);
            Asu[(4 * q + 3) * AS_STR + tid] = f2tf(v.w);
        }
        // stage W1 chunk (rows ch*64 .. +64), already k-major
        {
            const int kk   = tid >> 2;
            const int coff = (tid & 3) * 32;
            const float4* s4 = reinterpret_cast<const float4*>(W1 + (size_t)(ch * 64 + kk) * 128 + coff);
            uint4* d4 = reinterpret_cast<uint4*>(Bsu + kk * BS_STR + coff);
            #pragma unroll
            for (int r = 0; r < 8; ++r) {
                float4 v = s4[r];
                d4[r] = make_uint4(f2tf(v.x), f2tf(v.y), f2tf(v.z), f2tf(v.w));
            }
        }
        __syncthreads();

        const uint32_t* Ab = Asu + wm + g;
        const uint32_t* Bb = Bsu + wn + g;
        #pragma unroll 4
        for (int ks = 0; ks < 8; ++ks) {
            const int ka = (ks * 8 + tig) * AS_STR;
            const int kb = (ks * 8 + tig) * BS_STR;
            uint32_t bv[8][2];
            #pragma unroll
            for (int j = 0; j < 8; ++j) {
                bv[j][0] = Bb[kb + 8 * j];
                bv[j][1] = Bb[kb + 4 * BS_STR + 8 * j];
            }
            uint32_t av[4][4];
            #pragma unroll
            for (int i = 0; i < 4; ++i) {
                av[i][0] = Ab[ka + 16 * i];
                av[i][1] = Ab[ka + 16 * i + 8];
                av[i][2] = Ab[ka + 4 * AS_STR + 16 * i];
                av[i][3] = Ab[ka + 4 * AS_STR + 16 * i + 8];
            }
            #pragma unroll
            for (int i = 0; i < 4; ++i)
                #pragma unroll
                for (int j = 0; j < 8; ++j)
                    mma8(acc[i][j], av[i][0], av[i][1], av[i][2], av[i][3],
                         bv[j][0], bv[j][1]);
        }
        __syncthreads();
    }

    // ---- H = relu(acc + b1) -> H_s[k][m] (tf32), k = hidden index
    {
        float b1v[8][2];
        #pragma unroll
        for (int j = 0; j < 8; ++j) {
            b1v[j][0] = prm[wn + 8 * j + 2 * tig];
            b1v[j][1] = prm[wn + 8 * j + 2 * tig + 1];
        }
        #pragma unroll
        for (int i = 0; i < 4; ++i) {
            const int r0 = wm + 16 * i + g;
            #pragma unroll
            for (int j = 0; j < 8; ++j) {
                const int n0 = wn + 8 * j + 2 * tig;
                float h0 = fmaxf(acc[i][j][0] + b1v[j][0], 0.f);
                float h1 = fmaxf(acc[i][j][1] + b1v[j][1], 0.f);
                float h2 = fmaxf(acc[i][j][2] + b1v[j][0], 0.f);
                float h3 = fmaxf(acc[i][j][3] + b1v[j][1], 0.f);
                Hsu[n0 * AS_STR + r0]           = f2tf(h0);
                Hsu[(n0 + 1) * AS_STR + r0]     = f2tf(h1);
                Hsu[n0 * AS_STR + r0 + 8]       = f2tf(h2);
                Hsu[(n0 + 1) * AS_STR + r0 + 8] = f2tf(h3);
            }
        }
    }
    __syncthreads();

    // ======================= GEMM2: K = 128 =======================
    #pragma unroll
    for (int i = 0; i < 4; ++i)
        #pragma unroll
        for (int j = 0; j < 8; ++j)
            #pragma unroll
            for (int c = 0; c < 4; ++c) acc[i][j][c] = 0.f;

    {
        const uint32_t* Ab = Hsu + wm + g;
        const uint32_t* Bb = W2u + wn + g;
        #pragma unroll 4
        for (int ks = 0; ks < 16; ++ks) {
            const int ka = (ks * 8 + tig) * AS_STR;
            const int kb = (ks * 8 + tig) * BS_STR;
            uint32_t bv[8][2];
            #pragma unroll
            for (int j = 0; j < 8; ++j) {
                bv[j][0] = Bb[kb + 8 * j];
                bv[j][1] = Bb[kb + 4 * BS_STR + 8 * j];
            }
            uint32_t av[4][4];
            #pragma unroll
            for (int i = 0; i < 4; ++i) {
                av[i][0] = Ab[ka + 16 * i];
                av[i][1] = Ab[ka + 16 * i + 8];
                av[i][2] = Ab[ka + 4 * AS_STR + 16 * i];
                av[i][3] = Ab[ka + 4 * AS_STR + 16 * i + 8];
            }
            #pragma unroll
            for (int i = 0; i < 4; ++i)
                #pragma unroll
                for (int j = 0; j < 8; ++j)
                    mma8(acc[i][j], av[i][0], av[i][1], av[i][2], av[i][3],
                         bv[j][0], bv[j][1]);
        }
    }

    // ======================= LayerNorm epilogue =======================
    float b2v[8][2], gv[8][2], bev[8][2];
    #pragma unroll
    for (int j = 0; j < 8; ++j) {
        const int n0 = wn + 8 * j + 2 * tig;
        b2v[j][0] = prm[128 + n0]; b2v[j][1] = prm[128 + n0 + 1];
        gv[j][0]  = prm[256 + n0]; gv[j][1]  = prm[256 + n0 + 1];
        bev[j][0] = prm[384 + n0]; bev[j][1] = prm[384 + n0 + 1];
    }

    // add bias, per-row partial sums over this warp's 64 cols
    #pragma unroll
    for (int i = 0; i < 4; ++i) {
        float s0 = 0.f, q0 = 0.f, s1 = 0.f, q1 = 0.f;
        #pragma unroll
        for (int j = 0; j < 8; ++j) {
            float v0 = acc[i][j][0] + b2v[j][0];
            float v1 = acc[i][j][1] + b2v[j][1];
            float v2 = acc[i][j][2] + b2v[j][0];
            float v3 = acc[i][j][3] + b2v[j][1];
            acc[i][j][0] = v0; acc[i][j][1] = v1; acc[i][j][2] = v2; acc[i][j][3] = v3;
            s0 += v0 + v1; q0 += v0 * v0 + v1 * v1;
            s1 += v2 + v3; q1 += v2 * v2 + v3 * v3;
        }
        // reduce across the quad (lanes share g)
        #pragma unroll
        for (int m = 1; m < 4; m <<= 1) {
            s0 += __shfl_xor_sync(0xffffffffu, s0, m);
            q0 += __shfl_xor_sync(0xffffffffu, q0, m);
            s1 += __shfl_xor_sync(0xffffffffu, s1, m);
            q1 += __shfl_xor_sync(0xffffffffu, q1, m);
        }
        if (tig == 0) {
            const int r0 = wm + 16 * i + g;
            ps[wc * 256 + r0]           = s0;
            ps[wc * 256 + r0 + 8]       = s1;
            ps[512 + wc * 256 + r0]     = q0;
            ps[512 + wc * 256 + r0 + 8] = q1;
        }
    }
    __syncthreads();

    #pragma unroll
    for (int i = 0; i < 4; ++i) {
        const int r0 = wm + 16 * i + g;
        const int r1 = r0 + 8;
        float s0 = ps[r0] + ps[256 + r0];
        float q0 = ps[512 + r0] + ps[768 + r0];
        float s1 = ps[r1] + ps[256 + r1];
        float q1 = ps[512 + r1] + ps[768 + r1];
        const float mu0 = s0 * (1.f / 128.f);
        const float mu1 = s1 * (1.f / 128.f);
        const float rs0 = rsqrtf(q0 * (1.f / 128.f) - mu0 * mu0 + 1e-5f);
        const float rs1 = rsqrtf(q1 * (1.f / 128.f) - mu1 * mu1 + 1e-5f);
        const int eg0 = eb + r0;
        const int eg1 = eb + r1;
        if (eg0 < E) {
            float* orow = out + (size_t)eg0 * 128;
            #pragma unroll
            for (int j = 0; j < 8; ++j) {
                const int n0 = wn + 8 * j + 2 * tig;
                float o0 = (acc[i][j][0] - mu0) * rs0 * gv[j][0] + bev[j][0];
                float o1 = (acc[i][j][1] - mu0) * rs0 * gv[j][1] + bev[j][1];
                *reinterpret_cast<float2*>(orow + n0) = make_float2(o0, o1);
            }
        }
        if (eg1 < E) {
            float* orow = out + (size_t)eg1 * 128;
            #pragma unroll
            for (int j = 0; j < 8; ++j) {
                const int n0 = wn + 8 * j + 2 * tig;
                float o2 = (acc[i][j][2] - mu1) * rs1 * gv[j][0] + bev[j][0];
                float o3 = (acc[i][j][3] - mu1) * rs1 * gv[j][1] + bev[j][1];
                *reinterpret_cast<float2*>(orow + n0) = make_float2(o2, o3);
            }
        }
    }
}

extern "C" void kernel_launch(void* const* d_in, const int* in_sizes, int n_in,
                              void* d_out, int out_size)
{
    (void)n_in; (void)out_size;
    const float* node_attr = (const float*)d_in[0];
    const float* edge_attr = (const float*)d_in[1];
    const int*   senders   = (const int*)  d_in[2];
    const int*   receivers = (const int*)  d_in[3];
    const float* W1        = (const float*)d_in[4];
    const float* b1        = (const float*)d_in[5];
    const float* W2        = (const float*)d_in[6];
    const float* b2        = (const float*)d_in[7];
    const float* ln_gamma  = (const float*)d_in[8];
    const float* ln_beta   = (const float*)d_in[9];
    float* out = (float*)d_out;

    const int E = in_sizes[2];

    cudaFuncSetAttribute(edge_block_mma,
                         cudaFuncAttributeMaxDynamicSharedMemorySize, SMEM_BYTES);

    const int grid = (E + CTA_M - 1) / CTA_M;
    edge_block_mma<<<grid, THREADS, SMEM_BYTES>>>(
        node_attr, edge_attr, senders, receivers,
        W1, b1, W2, b2, ln_gamma, ln_beta, out, E);
}

// round 4
// speedup vs baseline: 2.7745x; 1.4643x over previous
#include <cuda_runtime.h>
#include <cstdint>

// EdgeBlock: out = LN( relu( [n[s]; n[r]; e] @ W1 + b1 ) @ W2 + b2 )
// tf32 mma.sync m16n8k8 + cp.async double-buffered staging.
//
// Prepass: convert W1/W2 to tf32 (round-to-nearest) into __device__ globals.
// Main: CTA = 256 edges, 8 warps 4(M)x2(N), warp tile 64x64.
//   A chunks [256 rows][k=64] staged row-major (stride 68) via cp.async (raw f32,
//   cvt at fragment load). B chunks = pre-cvt W1 rows, k-major (stride 136).
//   Double-buffered: chunk ch+1 in flight during chunk ch MMAs.
//   GEMM2: H [256][132] row-major (tf32 written at epilogue), W2 [128][136].

#define CTA_M   256
#define THREADS 256

// smem float offsets
#define OFF_A0   0        // [256][68] = 17408
#define OFF_A1   17408
#define OFF_B0   34816    // [64][136] = 8704
#define OFF_B1   43520    // ends 52224
#define OFF_H    0        // [256][132] = 33792 (phase 2, aliases A0/A1)
#define OFF_W2   33792    // [128][136] = 17408 (aliases B0/B1 tail) ends 51200
#define OFF_PRM  52224    // b1,b2,gamma,beta (512)
#define OFF_PS   52736    // LN partials (1024)
#define SMEM_FLOATS 53760
#define SMEM_BYTES  (SMEM_FLOATS * 4)

#define A_STR  68
#define B_STR  136
#define H_STR  132

__device__ uint32_t g_W1tf[384 * 128];
__device__ uint32_t g_W2tf[128 * 128];

__device__ __forceinline__ uint32_t f2tf(float f) {
    uint32_t u;
    asm("cvt.rna.tf32.f32 %0, %1;" : "=r"(u) : "f"(f));
    return u;
}
__device__ __forceinline__ uint32_t smem_u32(const void* p) {
    uint32_t a;
    asm("{ .reg .u64 t; cvta.to.shared.u64 t, %1; cvt.u32.u64 %0, t; }" : "=r"(a) : "l"(p));
    return a;
}
__device__ __forceinline__ void cp16(uint32_t dst, const void* src) {
    asm volatile("cp.async.cg.shared.global [%0], [%1], 16;" :: "r"(dst), "l"(src));
}
#define CP_COMMIT() asm volatile("cp.async.commit_group;" ::: "memory")
#define CP_WAIT0()  asm volatile("cp.async.wait_group 0;" ::: "memory")

__device__ __forceinline__ void mma8(float* d,
                                     uint32_t a0, uint32_t a1, uint32_t a2, uint32_t a3,
                                     uint32_t b0, uint32_t b1) {
    asm volatile(
        "mma.sync.aligned.m16n8k8.row.col.f32.tf32.tf32.f32 "
        "{%0,%1,%2,%3}, {%4,%5,%6,%7}, {%8,%9}, {%0,%1,%2,%3};"
        : "+f"(d[0]), "+f"(d[1]), "+f"(d[2]), "+f"(d[3])
        : "r"(a0), "r"(a1), "r"(a2), "r"(a3), "r"(b0), "r"(b1));
}

// ---------------- prepass: f32 -> tf32 weights ----------------
__global__ void cvt_weights(const float* __restrict__ W1, const float* __restrict__ W2) {
    int i = blockIdx.x * 256 + threadIdx.x;
    if (i < 384 * 128)       g_W1tf[i] = f2tf(W1[i]);
    int j = i - 384 * 128;
    if (j >= 0 && j < 128 * 128) g_W2tf[j] = f2tf(W2[j]);
}

// ---------------- main kernel ----------------
__global__ __launch_bounds__(THREADS, 1)
void edge_block_mma(const float* __restrict__ node_attr,
                    const float* __restrict__ edge_attr,
                    const int*   __restrict__ senders,
                    const int*   __restrict__ receivers,
                    const float* __restrict__ b1,
                    const float* __restrict__ b2,
                    const float* __restrict__ ln_g,
                    const float* __restrict__ ln_b,
                    float* __restrict__ out,
                    int E)
{
    extern __shared__ float smem[];
    float* prm = smem + OFF_PRM;
    float* ps  = smem + OFF_PS;

    const uint32_t sbase = smem_u32(smem);

    const int tid  = threadIdx.x;
    const int lane = tid & 31;
    const int wid  = tid >> 5;
    const int g    = lane >> 2;
    const int tig  = lane & 3;
    const int wm   = (wid >> 1) * 64;
    const int wn   = (wid & 1) * 64;
    const int wc   = wid & 1;
    const int eb   = blockIdx.x * CTA_M;

    if (tid < 128) {
        prm[tid]       = b1[tid];
        prm[128 + tid] = b2[tid];
        prm[256 + tid] = ln_g[tid];
        prm[384 + tid] = ln_b[tid];
    }

    int eg = eb + tid;
    if (eg >= E) eg = E - 1;
    const int sidx = senders[eg];
    const int ridx = receivers[eg];

    const float* rowbase[3] = {
        node_attr + (size_t)sidx * 128,
        node_attr + (size_t)ridx * 128,
        edge_attr + (size_t)eg  * 128
    };

    // per-thread staging addresses
    const int br  = tid >> 2;          // B row
    const int bs  = tid & 3;           // B quarter
    const uint32_t offA[2] = { sbase + OFF_A0 * 4u + (uint32_t)tid * (A_STR * 4u),
                               sbase + OFF_A1 * 4u + (uint32_t)tid * (A_STR * 4u) };
    const uint32_t offB[2] = { sbase + OFF_B0 * 4u + (uint32_t)(br * B_STR + bs * 32) * 4u,
                               sbase + OFF_B1 * 4u + (uint32_t)(br * B_STR + bs * 32) * 4u };

    auto issue_chunk = [&](int ch) {
        const int buf = ch & 1;
        const float* asrc = rowbase[ch >> 1] + (ch & 1) * 64;
        #pragma unroll
        for (int i = 0; i < 16; ++i)
            cp16(offA[buf] + i * 16, asrc + i * 4);
        const uint32_t* bsrc = g_W1tf + (size_t)(ch * 64 + br) * 128 + bs * 32;
        #pragma unroll
        for (int i = 0; i < 8; ++i)
            cp16(offB[buf] + i * 16, bsrc + i * 4);
    };

    float acc[4][8][4];
    #pragma unroll
    for (int i = 0; i < 4; ++i)
        #pragma unroll
        for (int j = 0; j < 8; ++j)
            #pragma unroll
            for (int c = 0; c < 4; ++c) acc[i][j][c] = 0.f;

    // prologue: chunk 0 in flight
    issue_chunk(0);
    CP_COMMIT();

    // ======================= GEMM1: 6 chunks of k=64 =======================
    #pragma unroll 1
    for (int ch = 0; ch < 6; ++ch) {
        CP_WAIT0();
        __syncthreads();          // chunk ch arrived everywhere; prev MMA done
        if (ch < 5) { issue_chunk(ch + 1); CP_COMMIT(); }

        const float*    Af = smem + (ch & 1 ? OFF_A1 : OFF_A0) + (wm + g) * A_STR;
        const uint32_t* Bf = reinterpret_cast<const uint32_t*>(smem + (ch & 1 ? OFF_B1 : OFF_B0)) + wn + g;

        #pragma unroll 4
        for (int ks = 0; ks < 8; ++ks) {
            const int ka = ks * 8 + tig;
            uint32_t bv[8][2];
            #pragma unroll
            for (int j = 0; j < 8; ++j) {
                bv[j][0] = Bf[ka * B_STR + 8 * j];
                bv[j][1] = Bf[(ka + 4) * B_STR + 8 * j];
            }
            uint32_t av[4][4];
            #pragma unroll
            for (int i = 0; i < 4; ++i) {
                av[i][0] = f2tf(Af[(16 * i)     * A_STR + ka]);
                av[i][1] = f2tf(Af[(16 * i + 8) * A_STR + ka]);
                av[i][2] = f2tf(Af[(16 * i)     * A_STR + ka + 4]);
                av[i][3] = f2tf(Af[(16 * i + 8) * A_STR + ka + 4]);
            }
            #pragma unroll
            for (int i = 0; i < 4; ++i)
                #pragma unroll
                for (int j = 0; j < 8; ++j)
                    mma8(acc[i][j], av[i][0], av[i][1], av[i][2], av[i][3],
                         bv[j][0], bv[j][1]);
        }
    }
    __syncthreads();   // GEMM1 done everywhere; buffers free for W2/H

    // ---- stage W2 (pre-cvt tf32) asynchronously; overlap with H write
    {
        const int row  = tid >> 1;
        const int half = tid & 1;
        const uint32_t dst = sbase + OFF_W2 * 4u + (uint32_t)(row * B_STR + half * 64) * 4u;
        const uint32_t* src = g_W2tf + (size_t)row * 128 + half * 64;
        #pragma unroll
        for (int i = 0; i < 16; ++i)
            cp16(dst + i * 16, src + i * 4);
        CP_COMMIT();
    }

    // ---- H = relu(acc + b1) -> H[m][k] as tf32
    {
        uint32_t* Hsu = reinterpret_cast<uint32_t*>(smem + OFF_H);
        float b1v[8][2];
        #pragma unroll
        for (int j = 0; j < 8; ++j) {
            b1v[j][0] = prm[wn + 8 * j + 2 * tig];
            b1v[j][1] = prm[wn + 8 * j + 2 * tig + 1];
        }
        #pragma unroll
        for (int i = 0; i < 4; ++i) {
            const int r0 = wm + 16 * i + g;
            #pragma unroll
            for (int j = 0; j < 8; ++j) {
                const int n0 = wn + 8 * j + 2 * tig;
                float h0 = fmaxf(acc[i][j][0] + b1v[j][0], 0.f);
                float h1 = fmaxf(acc[i][j][1] + b1v[j][1], 0.f);
                float h2 = fmaxf(acc[i][j][2] + b1v[j][0], 0.f);
                float h3 = fmaxf(acc[i][j][3] + b1v[j][1], 0.f);
                Hsu[r0 * H_STR + n0]           = f2tf(h0);
                Hsu[r0 * H_STR + n0 + 1]       = f2tf(h1);
                Hsu[(r0 + 8) * H_STR + n0]     = f2tf(h2);
                Hsu[(r0 + 8) * H_STR + n0 + 1] = f2tf(h3);
            }
        }
    }
    CP_WAIT0();
    __syncthreads();

    // ======================= GEMM2: K = 128 =======================
    #pragma unroll
    for (int i = 0; i < 4; ++i)
        #pragma unroll
        for (int j = 0; j < 8; ++j)
            #pragma unroll
            for (int c = 0; c < 4; ++c) acc[i][j][c] = 0.f;

    {
        const uint32_t* Hf = reinterpret_cast<const uint32_t*>(smem + OFF_H) + (wm + g) * H_STR;
        const uint32_t* Bf = reinterpret_cast<const uint32_t*>(smem + OFF_W2) + wn + g;
        #pragma unroll 4
        for (int ks = 0; ks < 16; ++ks) {
            const int ka = ks * 8 + tig;
            uint32_t bv[8][2];
            #pragma unroll
            for (int j = 0; j < 8; ++j) {
                bv[j][0] = Bf[ka * B_STR + 8 * j];
                bv[j][1] = Bf[(ka + 4) * B_STR + 8 * j];
            }
            uint32_t av[4][4];
            #pragma unroll
            for (int i = 0; i < 4; ++i) {
                av[i][0] = Hf[(16 * i)     * H_STR + ka];
                av[i][1] = Hf[(16 * i + 8) * H_STR + ka];
                av[i][2] = Hf[(16 * i)     * H_STR + ka + 4];
                av[i][3] = Hf[(16 * i + 8) * H_STR + ka + 4];
            }
            #pragma unroll
            for (int i = 0; i < 4; ++i)
                #pragma unroll
                for (int j = 0; j < 8; ++j)
                    mma8(acc[i][j], av[i][0], av[i][1], av[i][2], av[i][3],
                         bv[j][0], bv[j][1]);
        }
    }

    // ======================= LayerNorm epilogue =======================
    float b2v[8][2], gv[8][2], bev[8][2];
    #pragma unroll
    for (int j = 0; j < 8; ++j) {
        const int n0 = wn + 8 * j + 2 * tig;
        b2v[j][0] = prm[128 + n0]; b2v[j][1] = prm[128 + n0 + 1];
        gv[j][0]  = prm[256 + n0]; gv[j][1]  = prm[256 + n0 + 1];
        bev[j][0] = prm[384 + n0]; bev[j][1] = prm[384 + n0 + 1];
    }

    #pragma unroll
    for (int i = 0; i < 4; ++i) {
        float s0 = 0.f, q0 = 0.f, s1 = 0.f, q1 = 0.f;
        #pragma unroll
        for (int j = 0; j < 8; ++j) {
            float v0 = acc[i][j][0] + b2v[j][0];
            float v1 = acc[i][j][1] + b2v[j][1];
            float v2 = acc[i][j][2] + b2v[j][0];
            float v3 = acc[i][j][3] + b2v[j][1];
            acc[i][j][0] = v0; acc[i][j][1] = v1; acc[i][j][2] = v2; acc[i][j][3] = v3;
            s0 += v0 + v1; q0 += v0 * v0 + v1 * v1;
            s1 += v2 + v3; q1 += v2 * v2 + v3 * v3;
        }
        #pragma unroll
        for (int m = 1; m < 4; m <<= 1) {
            s0 += __shfl_xor_sync(0xffffffffu, s0, m);
            q0 += __shfl_xor_sync(0xffffffffu, q0, m);
            s1 += __shfl_xor_sync(0xffffffffu, s1, m);
            q1 += __shfl_xor_sync(0xffffffffu, q1, m);
        }
        if (tig == 0) {
            const int r0 = wm + 16 * i + g;
            ps[wc * 256 + r0]           = s0;
            ps[wc * 256 + r0 + 8]       = s1;
            ps[512 + wc * 256 + r0]     = q0;
            ps[512 + wc * 256 + r0 + 8] = q1;
        }
    }
    __syncthreads();

    #pragma unroll
    for (int i = 0; i < 4; ++i) {
        const int r0 = wm + 16 * i + g;
        const int r1 = r0 + 8;
        float s0 = ps[r0] + ps[256 + r0];
        float q0 = ps[512 + r0] + ps[768 + r0];
        float s1 = ps[r1] + ps[256 + r1];
        float q1 = ps[512 + r1] + ps[768 + r1];
        const float mu0 = s0 * (1.f / 128.f);
        const float mu1 = s1 * (1.f / 128.f);
        const float rs0 = rsqrtf(q0 * (1.f / 128.f) - mu0 * mu0 + 1e-5f);
        const float rs1 = rsqrtf(q1 * (1.f / 128.f) - mu1 * mu1 + 1e-5f);
        const int eg0 = eb + r0;
        const int eg1 = eb + r1;
        if (eg0 < E) {
            float* orow = out + (size_t)eg0 * 128;
            #pragma unroll
            for (int j = 0; j < 8; ++j) {
                const int n0 = wn + 8 * j + 2 * tig;
                float o0 = (acc[i][j][0] - mu0) * rs0 * gv[j][0] + bev[j][0];
                float o1 = (acc[i][j][1] - mu0) * rs0 * gv[j][1] + bev[j][1];
                *reinterpret_cast<float2*>(orow + n0) = make_float2(o0, o1);
            }
        }
        if (eg1 < E) {
            float* orow = out + (size_t)eg1 * 128;
            #pragma unroll
            for (int j = 0; j < 8; ++j) {
                const int n0 = wn + 8 * j + 2 * tig;
                float o2 = (acc[i][j][2] - mu1) * rs1 * gv[j][0] + bev[j][0];
                float o3 = (acc[i][j][3] - mu1) * rs1 * gv[j][1] + bev[j][1];
                *reinterpret_cast<float2*>(orow + n0) = make_float2(o2, o3);
            }
        }
    }
}

extern "C" void kernel_launch(void* const* d_in, const int* in_sizes, int n_in,
                              void* d_out, int out_size)
{
    (void)n_in; (void)out_size;
    const float* node_attr = (const float*)d_in[0];
    const float* edge_attr = (const float*)d_in[1];
    const int*   senders   = (const int*)  d_in[2];
    const int*   receivers = (const int*)  d_in[3];
    const float* W1        = (const float*)d_in[4];
    const float* b1        = (const float*)d_in[5];
    const float* W2        = (const float*)d_in[6];
    const float* b2        = (const float*)d_in[7];
    const float* ln_gamma  = (const float*)d_in[8];
    const float* ln_beta   = (const float*)d_in[9];
    float* out = (float*)d_out;

    const int E = in_sizes[2];

    cvt_weights<<<256, 256>>>(W1, W2);

    cudaFuncSetAttribute(edge_block_mma,
                         cudaFuncAttributeMaxDynamicSharedMemorySize, SMEM_BYTES);

    const int grid = (E + CTA_M - 1) / CTA_M;
    edge_block_mma<<<grid, THREADS, SMEM_BYTES>>>(
        node_attr, edge_attr, senders, receivers,
        b1, b2, ln_gamma, ln_beta, out, E);
}

// round 5
// speedup vs baseline: 2.9387x; 1.0592x over previous
#include <cuda_runtime.h>
#include <cstdint>

// EdgeBlock: out = LN( relu( [n[s]; n[r]; e] @ W1 + b1 ) @ W2 + b2 )
// tf32 mma.sync m16n8k8 + cp.async double buffering, 2 CTAs/SM.
//
// CTA = 128 edges, 256 threads, 8 warps in 4(M)x2(N); warp tile 32x64.
// GEMM1: K=384 in 12 chunks of 32 (A raw f32 row-major [128][36] via cp.async,
//        cvt at fragment load; B = pre-cvt tf32 W1 k-major [32][136]).
// GEMM2: K=128 in 4 chunks of 32; A = H (tf32, [128][132] row-major in smem),
//        B = W2 chunks streamed through the same B0/B1 slots.
// smem ~104 KB  -> 2 CTAs/SM; __launch_bounds__(256,2) -> <=128 regs.

#define CTA_M   128
#define THREADS 256

#define A_STR  36
#define B_STR  136
#define H_STR  132

// smem float offsets
#define OFF_H    0        // [128][132] = 16896 (phase 2)
#define OFF_A0   0        // [128][36] = 4608 (phase 1, aliases H)
#define OFF_A1   4608     // ends 9216
#define OFF_B0   16896    // [32][136] = 4352
#define OFF_B1   21248    // ends 25600
#define OFF_PRM  25600    // b1,b2,gamma,beta (512)
#define OFF_PS   26112    // LN partials (512)
#define SMEM_FLOATS 26624
#define SMEM_BYTES  (SMEM_FLOATS * 4)

__device__ uint32_t g_W1tf[384 * 128];
__device__ uint32_t g_W2tf[128 * 128];

__device__ __forceinline__ uint32_t f2tf(float f) {
    uint32_t u;
    asm("cvt.rna.tf32.f32 %0, %1;" : "=r"(u) : "f"(f));
    return u;
}
__device__ __forceinline__ uint32_t smem_u32(const void* p) {
    uint32_t a;
    asm("{ .reg .u64 t; cvta.to.shared.u64 t, %1; cvt.u32.u64 %0, t; }" : "=r"(a) : "l"(p));
    return a;
}
__device__ __forceinline__ void cp16(uint32_t dst, const void* src) {
    asm volatile("cp.async.cg.shared.global [%0], [%1], 16;" :: "r"(dst), "l"(src));
}
#define CP_COMMIT() asm volatile("cp.async.commit_group;" ::: "memory")
#define CP_WAIT0()  asm volatile("cp.async.wait_group 0;" ::: "memory")

__device__ __forceinline__ void mma8(float* d,
                                     uint32_t a0, uint32_t a1, uint32_t a2, uint32_t a3,
                                     uint32_t b0, uint32_t b1) {
    asm volatile(
        "mma.sync.aligned.m16n8k8.row.col.f32.tf32.tf32.f32 "
        "{%0,%1,%2,%3}, {%4,%5,%6,%7}, {%8,%9}, {%0,%1,%2,%3};"
        : "+f"(d[0]), "+f"(d[1]), "+f"(d[2]), "+f"(d[3])
        : "r"(a0), "r"(a1), "r"(a2), "r"(a3), "r"(b0), "r"(b1));
}

// ---------------- prepass: f32 -> tf32 weights ----------------
__global__ void cvt_weights(const float* __restrict__ W1, const float* __restrict__ W2) {
    int i = blockIdx.x * 256 + threadIdx.x;
    if (i < 384 * 128)           g_W1tf[i] = f2tf(W1[i]);
    int j = i - 384 * 128;
    if (j >= 0 && j < 128 * 128) g_W2tf[j] = f2tf(W2[j]);
}

// ---------------- main kernel ----------------
__global__ __launch_bounds__(THREADS, 2)
void edge_block_mma(const float* __restrict__ node_attr,
                    const float* __restrict__ edge_attr,
                    const int*   __restrict__ senders,
                    const int*   __restrict__ receivers,
                    const float* __restrict__ b1,
                    const float* __restrict__ b2,
                    const float* __restrict__ ln_g,
                    const float* __restrict__ ln_b,
                    float* __restrict__ out,
                    int E)
{
    extern __shared__ float smem[];
    float* prm = smem + OFF_PRM;
    float* ps  = smem + OFF_PS;

    const uint32_t sbase = smem_u32(smem);

    const int tid  = threadIdx.x;
    const int lane = tid & 31;
    const int wid  = tid >> 5;
    const int g    = lane >> 2;
    const int tig  = lane & 3;
    const int wm   = (wid >> 1) * 32;   // warp M offset (4 warps x 32 rows)
    const int wn   = (wid & 1) * 64;    // warp N offset
    const int wc   = wid & 1;
    const int eb   = blockIdx.x * CTA_M;

    if (tid < 128) {
        prm[tid]       = b1[tid];
        prm[128 + tid] = b2[tid];
        prm[256 + tid] = ln_g[tid];
        prm[384 + tid] = ln_b[tid];
    }

    // staging identity: thread handles row tid>>1, half tid&1 (16 floats)
    const int arow = tid >> 1;
    const int ahalf = tid & 1;
    int eg = eb + arow;
    if (eg >= E) eg = E - 1;
    const int sidx = senders[eg];
    const int ridx = receivers[eg];
    const float* rowbase[3] = {
        node_attr + (size_t)sidx * 128,
        node_attr + (size_t)ridx * 128,
        edge_attr + (size_t)eg  * 128
    };

    const uint32_t offA[2] = {
        sbase + (OFF_A0 + arow * A_STR + ahalf * 16) * 4u,
        sbase + (OFF_A1 + arow * A_STR + ahalf * 16) * 4u };
    const int brow = tid >> 3;          // 32 rows, 8 threads/row
    const int bcol = (tid & 7) * 16;
    const uint32_t offB[2] = {
        sbase + (OFF_B0 + brow * B_STR + bcol) * 4u,
        sbase + (OFF_B1 + brow * B_STR + bcol) * 4u };

    auto issue_chunk1 = [&](int ch) {
        const int buf = ch & 1;
        const float* asrc = rowbase[ch >> 2] + (ch & 3) * 32 + ahalf * 16;
        #pragma unroll
        for (int i = 0; i < 4; ++i)
            cp16(offA[buf] + i * 16, asrc + i * 4);
        const uint32_t* bsrc = g_W1tf + (size_t)(ch * 32 + brow) * 128 + bcol;
        #pragma unroll
        for (int i = 0; i < 4; ++i)
            cp16(offB[buf] + i * 16, bsrc + i * 4);
    };
    auto issue_w2 = [&](int ch) {
        const int buf = ch & 1;
        const uint32_t* bsrc = g_W2tf + (size_t)(ch * 32 + brow) * 128 + bcol;
        #pragma unroll
        for (int i = 0; i < 4; ++i)
            cp16(offB[buf] + i * 16, bsrc + i * 4);
    };

    float acc[2][8][4];
    #pragma unroll
    for (int i = 0; i < 2; ++i)
        #pragma unroll
        for (int j = 0; j < 8; ++j)
            #pragma unroll
            for (int c = 0; c < 4; ++c) acc[i][j][c] = 0.f;

    issue_chunk1(0);
    CP_COMMIT();

    // ======================= GEMM1: 12 chunks of k=32 =======================
    #pragma unroll 1
    for (int ch = 0; ch < 12; ++ch) {
        CP_WAIT0();
        __syncthreads();
        if (ch < 11) { issue_chunk1(ch + 1); CP_COMMIT(); }

        const float*    Af = smem + (ch & 1 ? OFF_A1 : OFF_A0) + (wm + g) * A_STR;
        const uint32_t* Bf = reinterpret_cast<const uint32_t*>(
                                 smem + (ch & 1 ? OFF_B1 : OFF_B0)) + wn + g;
        #pragma unroll
        for (int ks = 0; ks < 4; ++ks) {
            const int ka = ks * 8 + tig;
            uint32_t bv[8][2];
            #pragma unroll
            for (int j = 0; j < 8; ++j) {
                bv[j][0] = Bf[ka * B_STR + 8 * j];
                bv[j][1] = Bf[(ka + 4) * B_STR + 8 * j];
            }
            uint32_t av[2][4];
            #pragma unroll
            for (int i = 0; i < 2; ++i) {
                av[i][0] = f2tf(Af[(16 * i)     * A_STR + ka]);
                av[i][1] = f2tf(Af[(16 * i + 8) * A_STR + ka]);
                av[i][2] = f2tf(Af[(16 * i)     * A_STR + ka + 4]);
                av[i][3] = f2tf(Af[(16 * i + 8) * A_STR + ka + 4]);
            }
            #pragma unroll
            for (int i = 0; i < 2; ++i)
                #pragma unroll
                for (int j = 0; j < 8; ++j)
                    mma8(acc[i][j], av[i][0], av[i][1], av[i][2], av[i][3],
                         bv[j][0], bv[j][1]);
        }
    }
    __syncthreads();   // GEMM1 reads done; A region free for H, B slots free

    // W2 chunk 0 in flight while H is written
    issue_w2(0);
    CP_COMMIT();

    // ---- H = relu(acc + b1) -> H[m][k] tf32
    {
        uint32_t* Hsu = reinterpret_cast<uint32_t*>(smem + OFF_H);
        float b1v[8][2];
        #pragma unroll
        for (int j = 0; j < 8; ++j) {
            b1v[j][0] = prm[wn + 8 * j + 2 * tig];
            b1v[j][1] = prm[wn + 8 * j + 2 * tig + 1];
        }
        #pragma unroll
        for (int i = 0; i < 2; ++i) {
            const int r0 = wm + 16 * i + g;
            #pragma unroll
            for (int j = 0; j < 8; ++j) {
                const int n0 = wn + 8 * j + 2 * tig;
                float h0 = fmaxf(acc[i][j][0] + b1v[j][0], 0.f);
                float h1 = fmaxf(acc[i][j][1] + b1v[j][1], 0.f);
                float h2 = fmaxf(acc[i][j][2] + b1v[j][0], 0.f);
                float h3 = fmaxf(acc[i][j][3] + b1v[j][1], 0.f);
                Hsu[r0 * H_STR + n0]           = f2tf(h0);
                Hsu[r0 * H_STR + n0 + 1]       = f2tf(h1);
                Hsu[(r0 + 8) * H_STR + n0]     = f2tf(h2);
                Hsu[(r0 + 8) * H_STR + n0 + 1] = f2tf(h3);
            }
        }
    }

    #pragma unroll
    for (int i = 0; i < 2; ++i)
        #pragma unroll
        for (int j = 0; j < 8; ++j)
            #pragma unroll
            for (int c = 0; c < 4; ++c) acc[i][j][c] = 0.f;

    // ======================= GEMM2: 4 chunks of k=32 =======================
    #pragma unroll 1
    for (int ch = 0; ch < 4; ++ch) {
        CP_WAIT0();
        __syncthreads();   // W2 chunk + (ch==0: H writes) visible
        if (ch < 3) { issue_w2(ch + 1); CP_COMMIT(); }

        const uint32_t* Hf = reinterpret_cast<const uint32_t*>(smem + OFF_H)
                             + (wm + g) * H_STR + ch * 32;
        const uint32_t* Bf = reinterpret_cast<const uint32_t*>(
                                 smem + (ch & 1 ? OFF_B1 : OFF_B0)) + wn + g;
        #pragma unroll
        for (int ks = 0; ks < 4; ++ks) {
            const int ka = ks * 8 + tig;
            uint32_t bv[8][2];
            #pragma unroll
            for (int j = 0; j < 8; ++j) {
                bv[j][0] = Bf[ka * B_STR + 8 * j];
                bv[j][1] = Bf[(ka + 4) * B_STR + 8 * j];
            }
            uint32_t av[2][4];
            #pragma unroll
            for (int i = 0; i < 2; ++i) {
                av[i][0] = Hf[(16 * i)     * H_STR + ka];
                av[i][1] = Hf[(16 * i + 8) * H_STR + ka];
                av[i][2] = Hf[(16 * i)     * H_STR + ka + 4];
                av[i][3] = Hf[(16 * i + 8) * H_STR + ka + 4];
            }
            #pragma unroll
            for (int i = 0; i < 2; ++i)
                #pragma unroll
                for (int j = 0; j < 8; ++j)
                    mma8(acc[i][j], av[i][0], av[i][1], av[i][2], av[i][3],
                         bv[j][0], bv[j][1]);
        }
    }

    // ======================= LayerNorm epilogue =======================
    float b2v[8][2], gv[8][2], bev[8][2];
    #pragma unroll
    for (int j = 0; j < 8; ++j) {
        const int n0 = wn + 8 * j + 2 * tig;
        b2v[j][0] = prm[128 + n0]; b2v[j][1] = prm[128 + n0 + 1];
        gv[j][0]  = prm[256 + n0]; gv[j][1]  = prm[256 + n0 + 1];
        bev[j][0] = prm[384 + n0]; bev[j][1] = prm[384 + n0 + 1];
    }

    #pragma unroll
    for (int i = 0; i < 2; ++i) {
        float s0 = 0.f, q0 = 0.f, s1 = 0.f, q1 = 0.f;
        #pragma unroll
        for (int j = 0; j < 8; ++j) {
            float v0 = acc[i][j][0] + b2v[j][0];
            float v1 = acc[i][j][1] + b2v[j][1];
            float v2 = acc[i][j][2] + b2v[j][0];
            float v3 = acc[i][j][3] + b2v[j][1];
            acc[i][j][0] = v0; acc[i][j][1] = v1; acc[i][j][2] = v2; acc[i][j][3] = v3;
            s0 += v0 + v1; q0 += v0 * v0 + v1 * v1;
            s1 += v2 + v3; q1 += v2 * v2 + v3 * v3;
        }
        #pragma unroll
        for (int m = 1; m < 4; m <<= 1) {
            s0 += __shfl_xor_sync(0xffffffffu, s0, m);
            q0 += __shfl_xor_sync(0xffffffffu, q0, m);
            s1 += __shfl_xor_sync(0xffffffffu, s1, m);
            q1 += __shfl_xor_sync(0xffffffffu, q1, m);
        }
        if (tig == 0) {
            const int r0 = wm + 16 * i + g;
            ps[wc * 128 + r0]           = s0;
            ps[wc * 128 + r0 + 8]       = s1;
            ps[256 + wc * 128 + r0]     = q0;
            ps[256 + wc * 128 + r0 + 8] = q1;
        }
    }
    __syncthreads();

    #pragma unroll
    for (int i = 0; i < 2; ++i) {
        const int r0 = wm + 16 * i + g;
        const int r1 = r0 + 8;
        float s0 = ps[r0] + ps[128 + r0];
        float q0 = ps[256 + r0] + ps[384 + r0];
        float s1 = ps[r1] + ps[128 + r1];
        float q1 = ps[256 + r1] + ps[384 + r1];
        const float mu0 = s0 * (1.f / 128.f);
        const float mu1 = s1 * (1.f / 128.f);
        const float rs0 = rsqrtf(q0 * (1.f / 128.f) - mu0 * mu0 + 1e-5f);
        const float rs1 = rsqrtf(q1 * (1.f / 128.f) - mu1 * mu1 + 1e-5f);
        const int eg0 = eb + r0;
        const int eg1 = eb + r1;
        if (eg0 < E) {
            float* orow = out + (size_t)eg0 * 128;
            #pragma unroll
            for (int j = 0; j < 8; ++j) {
                const int n0 = wn + 8 * j + 2 * tig;
                float o0 = (acc[i][j][0] - mu0) * rs0 * gv[j][0] + bev[j][0];
                float o1 = (acc[i][j][1] - mu0) * rs0 * gv[j][1] + bev[j][1];
                *reinterpret_cast<float2*>(orow + n0) = make_float2(o0, o1);
            }
        }
        if (eg1 < E) {
            float* orow = out + (size_t)eg1 * 128;
            #pragma unroll
            for (int j = 0; j < 8; ++j) {
                const int n0 = wn + 8 * j + 2 * tig;
                float o2 = (acc[i][j][2] - mu1) * rs1 * gv[j][0] + bev[j][0];
                float o3 = (acc[i][j][3] - mu1) * rs1 * gv[j][1] + bev[j][1];
                *reinterpret_cast<float2*>(orow + n0) = make_float2(o2, o3);
            }
        }
    }
}

extern "C" void kernel_launch(void* const* d_in, const int* in_sizes, int n_in,
                              void* d_out, int out_size)
{
    (void)n_in; (void)out_size;
    const float* node_attr = (const float*)d_in[0];
    const float* edge_attr = (const float*)d_in[1];
    const int*   senders   = (const int*)  d_in[2];
    const int*   receivers = (const int*)  d_in[3];
    const float* W1        = (const float*)d_in[4];
    const float* b1        = (const float*)d_in[5];
    const float* W2        = (const float*)d_in[6];
    const float* b2        = (const float*)d_in[7];
    const float* ln_gamma  = (const float*)d_in[8];
    const float* ln_beta   = (const float*)d_in[9];
    float* out = (float*)d_out;

    const int E = in_sizes[2];

    cvt_weights<<<256, 256>>>(W1, W2);

    cudaFuncSetAttribute(edge_block_mma,
                         cudaFuncAttributeMaxDynamicSharedMemorySize, SMEM_BYTES);

    const int grid = (E + CTA_M - 1) / CTA_M;
    edge_block_mma<<<grid, THREADS, SMEM_BYTES>>>(
        node_attr, edge_attr, senders, receivers,
        b1, b2, ln_gamma, ln_beta, out, E);
}

// round 6
// speedup vs baseline: 3.7299x; 1.2693x over previous
#include <cuda_runtime.h>
#include <cstdint>

// EdgeBlock: out = LN( relu( [n[s]; n[r]; e] @ W1 + b1 ) @ W2 + b2 )
// tf32 mma.sync m16n8k8 + cp.async double buffering, 2 CTAs/SM.
//
// Weights are pre-permuted (prepass) into fragment order so B-fragment loads
// are 4x LDS.128 per k-step instead of 16 scalar LDS.
// Layout per k32-chunk: blocks [ks(4)][half(2)][tig(4)] of 33 float4
// (32 data + 1 pad); block holds, for g=0..7, the 16 floats
// { B[k=8ks+tig+4p][n=half*64+g+8j] : j=0..7, p=0..1 } at float idx g*16+j*2+p.
//
// CTA = 128 edges, 256 threads, 8 warps 4(M)x2(N), warp tile 32x64.
// GEMM1: K=384, 12 chunks of 32. GEMM2: K=128, 4 chunks of 32 (W2 streamed).

#define CTA_M   128
#define THREADS 256

#define A_STR  36
#define H_STR  136
#define B_CHUNK_FL 4224   // 32 blocks * 132 floats

// smem float offsets
#define OFF_H    0        // [128][136] = 17408 (phase 2)
#define OFF_A0   0        // [128][36] = 4608 (phase 1, aliases H)
#define OFF_A1   4608     // ends 9216
#define OFF_B0   17408    // 4224
#define OFF_B1   21632    // ends 25856
#define OFF_PRM  25856    // b1,b2,gamma,beta (512)
#define OFF_PS   26368    // LN partials (512)
#define SMEM_FLOATS 26880
#define SMEM_BYTES  (SMEM_FLOATS * 4)

__device__ uint32_t g_W1p[12 * B_CHUNK_FL];   // 50688
__device__ uint32_t g_W2p[4 * B_CHUNK_FL];    // 16896

__device__ __forceinline__ uint32_t f2tf(float f) {
    uint32_t u;
    asm("cvt.rna.tf32.f32 %0, %1;" : "=r"(u) : "f"(f));
    return u;
}
__device__ __forceinline__ uint32_t smem_u32(const void* p) {
    uint32_t a;
    asm("{ .reg .u64 t; cvta.to.shared.u64 t, %1; cvt.u32.u64 %0, t; }" : "=r"(a) : "l"(p));
    return a;
}
__device__ __forceinline__ void cp16(uint32_t dst, const void* src) {
    asm volatile("cp.async.cg.shared.global [%0], [%1], 16;" :: "r"(dst), "l"(src));
}
#define CP_COMMIT() asm volatile("cp.async.commit_group;" ::: "memory")
#define CP_WAIT0()  asm volatile("cp.async.wait_group 0;" ::: "memory")

__device__ __forceinline__ void mma8(float* d,
                                     uint32_t a0, uint32_t a1, uint32_t a2, uint32_t a3,
                                     uint32_t b0, uint32_t b1) {
    asm volatile(
        "mma.sync.aligned.m16n8k8.row.col.f32.tf32.tf32.f32 "
        "{%0,%1,%2,%3}, {%4,%5,%6,%7}, {%8,%9}, {%0,%1,%2,%3};"
        : "+f"(d[0]), "+f"(d[1]), "+f"(d[2]), "+f"(d[3])
        : "r"(a0), "r"(a1), "r"(a2), "r"(a3), "r"(b0), "r"(b1));
}

// ---------------- prepass: permute + cvt weights into fragment order ----------------
__global__ void pack_weights(const float* __restrict__ W1, const float* __restrict__ W2) {
    int i = blockIdx.x * 256 + threadIdx.x;   // 256 blocks -> 65536 threads
    const float* src;
    uint32_t* dst;
    int k, n;
    if (i < 384 * 128) {
        k = i >> 7; n = i & 127; src = W1; dst = g_W1p;
    } else {
        int i2 = i - 384 * 128;
        if (i2 >= 128 * 128) return;
        k = i2 >> 7; n = i2 & 127; src = W2; dst = g_W2p;
    }
    const int chunk = k >> 5;
    const int kk    = k & 31;
    const int ks    = kk >> 3;
    const int tg    = kk & 3;
    const int p     = (kk >> 2) & 1;
    const int half  = n >> 6;
    const int g     = n & 7;
    const int j     = (n & 63) >> 3;
    const int dest  = chunk * B_CHUNK_FL +
                      ((ks * 2 + half) * 4 + tg) * 132 + g * 16 + j * 2 + p;
    dst[dest] = f2tf(src[(size_t)k * 128 + n]);
}

// ---------------- main kernel ----------------
__global__ __launch_bounds__(THREADS, 2)
void edge_block_mma(const float* __restrict__ node_attr,
                    const float* __restrict__ edge_attr,
                    const int*   __restrict__ senders,
                    const int*   __restrict__ receivers,
                    const float* __restrict__ b1,
                    const float* __restrict__ b2,
                    const float* __restrict__ ln_g,
                    const float* __restrict__ ln_b,
                    float* __restrict__ out,
                    int E)
{
    extern __shared__ float smem[];
    float* prm = smem + OFF_PRM;
    float* ps  = smem + OFF_PS;

    const uint32_t sbase = smem_u32(smem);

    const int tid  = threadIdx.x;
    const int lane = tid & 31;
    const int wid  = tid >> 5;
    const int g    = lane >> 2;
    const int tig  = lane & 3;
    const int wm   = (wid >> 1) * 32;
    const int wn   = (wid & 1) * 64;
    const int wc   = wid & 1;
    const int eb   = blockIdx.x * CTA_M;

    if (tid < 128) {
        prm[tid]       = b1[tid];
        prm[128 + tid] = b2[tid];
        prm[256 + tid] = ln_g[tid];
        prm[384 + tid] = ln_b[tid];
    }

    // gather identity: thread handles row tid>>1, half tid&1
    const int arow  = tid >> 1;
    const int ahalf = tid & 1;
    int eg = eb + arow;
    if (eg >= E) eg = E - 1;
    const int sidx = senders[eg];
    const int ridx = receivers[eg];
    const float* base_s = node_attr + (size_t)sidx * 128;
    const float* base_r = node_attr + (size_t)ridx * 128;
    const float* base_e = edge_attr + (size_t)eg  * 128;

    const uint32_t offA[2] = {
        sbase + (OFF_A0 + arow * A_STR + ahalf * 16) * 4u,
        sbase + (OFF_A1 + arow * A_STR + ahalf * 16) * 4u };
    const uint32_t offB[2] = { sbase + OFF_B0 * 4u, sbase + OFF_B1 * 4u };

    // B chunk copy: 1056 float4 per chunk; 256 threads x4 + first 32 x1
    auto copy_bchunk = [&](const uint32_t* gsrc, int buf) {
        const uint32_t dstb = offB[buf];
        #pragma unroll
        for (int r = 0; r < 4; ++r)
            cp16(dstb + (tid + 256 * r) * 16u, gsrc + (tid + 256 * r) * 4);
        if (tid < 32)
            cp16(dstb + (1024 + tid) * 16u, gsrc + (1024 + tid) * 4);
    };

    auto issue_chunk1 = [&](int ch) {
        const int buf = ch & 1;
        const int sel = ch >> 2;
        const float* ab = (sel == 0) ? base_s : ((sel == 1) ? base_r : base_e);
        const float* asrc = ab + (ch & 3) * 32 + ahalf * 16;
        #pragma unroll
        for (int i = 0; i < 4; ++i)
            cp16(offA[buf] + i * 16, asrc + i * 4);
        copy_bchunk(g_W1p + (size_t)ch * B_CHUNK_FL, buf);
    };
    auto issue_w2 = [&](int ch) {
        copy_bchunk(g_W2p + (size_t)ch * B_CHUNK_FL, ch & 1);
    };

    float acc[2][8][4];
    #pragma unroll
    for (int i = 0; i < 2; ++i)
        #pragma unroll
        for (int j = 0; j < 8; ++j)
            #pragma unroll
            for (int c = 0; c < 4; ++c) acc[i][j][c] = 0.f;

    issue_chunk1(0);
    CP_COMMIT();

    const int halfsel = wn >> 6;

    // ======================= GEMM1: 12 chunks of k=32 =======================
    #pragma unroll 1
    for (int ch = 0; ch < 12; ++ch) {
        CP_WAIT0();
        __syncthreads();
        if (ch < 11) { issue_chunk1(ch + 1); CP_COMMIT(); }

        const float* Af = smem + (ch & 1 ? OFF_A1 : OFF_A0) + (wm + g) * A_STR;
        const uint4* Bq = reinterpret_cast<const uint4*>(
                              smem + (ch & 1 ? OFF_B1 : OFF_B0));
        #pragma unroll
        for (int ks = 0; ks < 4; ++ks) {
            const int ka = ks * 8 + tig;
            const uint4* bp = Bq + (size_t)((ks * 2 + halfsel) * 4 + tig) * 33 + g * 4;
            uint4 r0 = bp[0], r1 = bp[1], r2 = bp[2], r3 = bp[3];
            uint32_t av[2][4];
            #pragma unroll
            for (int i = 0; i < 2; ++i) {
                av[i][0] = f2tf(Af[(16 * i)     * A_STR + ka]);
                av[i][1] = f2tf(Af[(16 * i + 8) * A_STR + ka]);
                av[i][2] = f2tf(Af[(16 * i)     * A_STR + ka + 4]);
                av[i][3] = f2tf(Af[(16 * i + 8) * A_STR + ka + 4]);
            }
            #pragma unroll
            for (int i = 0; i < 2; ++i) {
                mma8(acc[i][0], av[i][0], av[i][1], av[i][2], av[i][3], r0.x, r0.y);
                mma8(acc[i][1], av[i][0], av[i][1], av[i][2], av[i][3], r0.z, r0.w);
                mma8(acc[i][2], av[i][0], av[i][1], av[i][2], av[i][3], r1.x, r1.y);
                mma8(acc[i][3], av[i][0], av[i][1], av[i][2], av[i][3], r1.z, r1.w);
                mma8(acc[i][4], av[i][0], av[i][1], av[i][2], av[i][3], r2.x, r2.y);
                mma8(acc[i][5], av[i][0], av[i][1], av[i][2], av[i][3], r2.z, r2.w);
                mma8(acc[i][6], av[i][0], av[i][1], av[i][2], av[i][3], r3.x, r3.y);
                mma8(acc[i][7], av[i][0], av[i][1], av[i][2], av[i][3], r3.z, r3.w);
            }
        }
    }
    __syncthreads();   // GEMM1 reads done; A region free for H, B slots free

    issue_w2(0);
    CP_COMMIT();

    // ---- H = relu(acc + b1) -> H[m][k] tf32 (STS.64 pairs)
    {
        uint32_t* Hsu = reinterpret_cast<uint32_t*>(smem + OFF_H);
        float b1v[8][2];
        #pragma unroll
        for (int j = 0; j < 8; ++j) {
            b1v[j][0] = prm[wn + 8 * j + 2 * tig];
            b1v[j][1] = prm[wn + 8 * j + 2 * tig + 1];
        }
        #pragma unroll
        for (int i = 0; i < 2; ++i) {
            const int r0 = wm + 16 * i + g;
            #pragma unroll
            for (int j = 0; j < 8; ++j) {
                const int n0 = wn + 8 * j + 2 * tig;
                uint2 h01 = make_uint2(f2tf(fmaxf(acc[i][j][0] + b1v[j][0], 0.f)),
                                       f2tf(fmaxf(acc[i][j][1] + b1v[j][1], 0.f)));
                uint2 h23 = make_uint2(f2tf(fmaxf(acc[i][j][2] + b1v[j][0], 0.f)),
                                       f2tf(fmaxf(acc[i][j][3] + b1v[j][1], 0.f)));
                *reinterpret_cast<uint2*>(&Hsu[r0 * H_STR + n0])       = h01;
                *reinterpret_cast<uint2*>(&Hsu[(r0 + 8) * H_STR + n0]) = h23;
            }
        }
    }

    #pragma unroll
    for (int i = 0; i < 2; ++i)
        #pragma unroll
        for (int j = 0; j < 8; ++j)
            #pragma unroll
            for (int c = 0; c < 4; ++c) acc[i][j][c] = 0.f;

    // ======================= GEMM2: 4 chunks of k=32 =======================
    #pragma unroll 1
    for (int ch = 0; ch < 4; ++ch) {
        CP_WAIT0();
        __syncthreads();
        if (ch < 3) { issue_w2(ch + 1); CP_COMMIT(); }

        const uint32_t* Hf = reinterpret_cast<const uint32_t*>(smem + OFF_H)
                             + (wm + g) * H_STR + ch * 32;
        const uint4* Bq = reinterpret_cast<const uint4*>(
                              smem + (ch & 1 ? OFF_B1 : OFF_B0));
        #pragma unroll
        for (int ks = 0; ks < 4; ++ks) {
            const int ka = ks * 8 + tig;
            const uint4* bp = Bq + (size_t)((ks * 2 + halfsel) * 4 + tig) * 33 + g * 4;
            uint4 r0 = bp[0], r1 = bp[1], r2 = bp[2], r3 = bp[3];
            uint32_t av[2][4];
            #pragma unroll
            for (int i = 0; i < 2; ++i) {
                av[i][0] = Hf[(16 * i)     * H_STR + ka];
                av[i][1] = Hf[(16 * i + 8) * H_STR + ka];
                av[i][2] = Hf[(16 * i)     * H_STR + ka + 4];
                av[i][3] = Hf[(16 * i + 8) * H_STR + ka + 4];
            }
            #pragma unroll
            for (int i = 0; i < 2; ++i) {
                mma8(acc[i][0], av[i][0], av[i][1], av[i][2], av[i][3], r0.x, r0.y);
                mma8(acc[i][1], av[i][0], av[i][1], av[i][2], av[i][3], r0.z, r0.w);
                mma8(acc[i][2], av[i][0], av[i][1], av[i][2], av[i][3], r1.x, r1.y);
                mma8(acc[i][3], av[i][0], av[i][1], av[i][2], av[i][3], r1.z, r1.w);
                mma8(acc[i][4], av[i][0], av[i][1], av[i][2], av[i][3], r2.x, r2.y);
                mma8(acc[i][5], av[i][0], av[i][1], av[i][2], av[i][3], r2.z, r2.w);
                mma8(acc[i][6], av[i][0], av[i][1], av[i][2], av[i][3], r3.x, r3.y);
                mma8(acc[i][7], av[i][0], av[i][1], av[i][2], av[i][3], r3.z, r3.w);
            }
        }
    }

    // ======================= LayerNorm epilogue =======================
    float b2v[8][2], gv[8][2], bev[8][2];
    #pragma unroll
    for (int j = 0; j < 8; ++j) {
        const int n0 = wn + 8 * j + 2 * tig;
        b2v[j][0] = prm[128 + n0]; b2v[j][1] = prm[128 + n0 + 1];
        gv[j][0]  = prm[256 + n0]; gv[j][1]  = prm[256 + n0 + 1];
        bev[j][0] = prm[384 + n0]; bev[j][1] = prm[384 + n0 + 1];
    }

    #pragma unroll
    for (int i = 0; i < 2; ++i) {
        float s0 = 0.f, q0 = 0.f, s1 = 0.f, q1 = 0.f;
        #pragma unroll
        for (int j = 0; j < 8; ++j) {
            float v0 = acc[i][j][0] + b2v[j][0];
            float v1 = acc[i][j][1] + b2v[j][1];
            float v2 = acc[i][j][2] + b2v[j][0];
            float v3 = acc[i][j][3] + b2v[j][1];
            acc[i][j][0] = v0; acc[i][j][1] = v1; acc[i][j][2] = v2; acc[i][j][3] = v3;
            s0 += v0 + v1; q0 += v0 * v0 + v1 * v1;
            s1 += v2 + v3; q1 += v2 * v2 + v3 * v3;
        }
        #pragma unroll
        for (int m = 1; m < 4; m <<= 1) {
            s0 += __shfl_xor_sync(0xffffffffu, s0, m);
            q0 += __shfl_xor_sync(0xffffffffu, q0, m);
            s1 += __shfl_xor_sync(0xffffffffu, s1, m);
            q1 += __shfl_xor_sync(0xffffffffu, q1, m);
        }
        if (tig == 0) {
            const int r0 = wm + 16 * i + g;
            ps[wc * 128 + r0]           = s0;
            ps[wc * 128 + r0 + 8]       = s1;
            ps[256 + wc * 128 + r0]     = q0;
            ps[256 + wc * 128 + r0 + 8] = q1;
        }
    }
    __syncthreads();

    #pragma unroll
    for (int i = 0; i < 2; ++i) {
        const int r0 = wm + 16 * i + g;
        const int r1 = r0 + 8;
        float s0 = ps[r0] + ps[128 + r0];
        float q0 = ps[256 + r0] + ps[384 + r0];
        float s1 = ps[r1] + ps[128 + r1];
        float q1 = ps[256 + r1] + ps[384 + r1];
        const float mu0 = s0 * (1.f / 128.f);
        const float mu1 = s1 * (1.f / 128.f);
        const float rs0 = rsqrtf(q0 * (1.f / 128.f) - mu0 * mu0 + 1e-5f);
        const float rs1 = rsqrtf(q1 * (1.f / 128.f) - mu1 * mu1 + 1e-5f);
        const int eg0 = eb + r0;
        const int eg1 = eb + r1;
        if (eg0 < E) {
            float* orow = out + (size_t)eg0 * 128;
            #pragma unroll
            for (int j = 0; j < 8; ++j) {
                const int n0 = wn + 8 * j + 2 * tig;
                float o0 = (acc[i][j][0] - mu0) * rs0 * gv[j][0] + bev[j][0];
                float o1 = (acc[i][j][1] - mu0) * rs0 * gv[j][1] + bev[j][1];
                *reinterpret_cast<float2*>(orow + n0) = make_float2(o0, o1);
            }
        }
        if (eg1 < E) {
            float* orow = out + (size_t)eg1 * 128;
            #pragma unroll
            for (int j = 0; j < 8; ++j) {
                const int n0 = wn + 8 * j + 2 * tig;
                float o2 = (acc[i][j][2] - mu1) * rs1 * gv[j][0] + bev[j][0];
                float o3 = (acc[i][j][3] - mu1) * rs1 * gv[j][1] + bev[j][1];
                *reinterpret_cast<float2*>(orow + n0) = make_float2(o2, o3);
            }
        }
    }
}

extern "C" void kernel_launch(void* const* d_in, const int* in_sizes, int n_in,
                              void* d_out, int out_size)
{
    (void)n_in; (void)out_size;
    const float* node_attr = (const float*)d_in[0];
    const float* edge_attr = (const float*)d_in[1];
    const int*   senders   = (const int*)  d_in[2];
    const int*   receivers = (const int*)  d_in[3];
    const float* W1        = (const float*)d_in[4];
    const float* b1        = (const float*)d_in[5];
    const float* W2        = (const float*)d_in[6];
    const float* b2        = (const float*)d_in[7];
    const float* ln_gamma  = (const float*)d_in[8];
    const float* ln_beta   = (const float*)d_in[9];
    float* out = (float*)d_out;

    const int E = in_sizes[2];

    pack_weights<<<256, 256>>>(W1, W2);

    cudaFuncSetAttribute(edge_block_mma,
                         cudaFuncAttributeMaxDynamicSharedMemorySize, SMEM_BYTES);

    const int grid = (E + CTA_M - 1) / CTA_M;
    edge_block_mma<<<grid, THREADS, SMEM_BYTES>>>(
        node_attr, edge_attr, senders, receivers,
        b1, b2, ln_gamma, ln_beta, out, E);
}

// round 7
// speedup vs baseline: 3.7307x; 1.0002x over previous
#include <cuda_runtime.h>
#include <cstdint>

// EdgeBlock: out = LN( relu( [n[s]; n[r]; e] @ W1 + b1 ) @ W2 + b2 )
// tf32 mma.sync m16n8k8 + cp.async double buffering, 2 CTAs/SM.
// R7: intra-chunk A-fragment software pipelining + per-warp ks stagger +
//     W2 chunk-0 copy overlapped with last GEMM1 chunk.
//
// Weights pre-permuted into fragment order (LDS.128 B loads), see pack_weights.
// CTA = 128 edges, 256 threads, 8 warps 4(M)x2(N), warp tile 32x64.

#define CTA_M   128
#define THREADS 256

#define A_STR  36
#define H_STR  136
#define B_CHUNK_FL 4224   // 32 blocks * 132 floats

// smem float offsets
#define OFF_H    0        // [128][136] = 17408 (phase 2)
#define OFF_A0   0        // [128][36] = 4608 (phase 1, aliases H)
#define OFF_A1   4608     // ends 9216
#define OFF_B0   17408    // 4224
#define OFF_B1   21632    // ends 25856
#define OFF_PRM  25856    // b1,b2,gamma,beta (512)
#define OFF_PS   26368    // LN partials (512)
#define SMEM_FLOATS 26880
#define SMEM_BYTES  (SMEM_FLOATS * 4)

__device__ uint32_t g_W1p[12 * B_CHUNK_FL];
__device__ uint32_t g_W2p[4 * B_CHUNK_FL];

__device__ __forceinline__ uint32_t f2tf(float f) {
    uint32_t u;
    asm("cvt.rna.tf32.f32 %0, %1;" : "=r"(u) : "f"(f));
    return u;
}
__device__ __forceinline__ uint32_t smem_u32(const void* p) {
    uint32_t a;
    asm("{ .reg .u64 t; cvta.to.shared.u64 t, %1; cvt.u32.u64 %0, t; }" : "=r"(a) : "l"(p));
    return a;
}
__device__ __forceinline__ void cp16(uint32_t dst, const void* src) {
    asm volatile("cp.async.cg.shared.global [%0], [%1], 16;" :: "r"(dst), "l"(src));
}
#define CP_COMMIT() asm volatile("cp.async.commit_group;" ::: "memory")
#define CP_WAIT0()  asm volatile("cp.async.wait_group 0;" ::: "memory")

__device__ __forceinline__ void mma8(float* d,
                                     uint32_t a0, uint32_t a1, uint32_t a2, uint32_t a3,
                                     uint32_t b0, uint32_t b1) {
    asm volatile(
        "mma.sync.aligned.m16n8k8.row.col.f32.tf32.tf32.f32 "
        "{%0,%1,%2,%3}, {%4,%5,%6,%7}, {%8,%9}, {%0,%1,%2,%3};"
        : "+f"(d[0]), "+f"(d[1]), "+f"(d[2]), "+f"(d[3])
        : "r"(a0), "r"(a1), "r"(a2), "r"(a3), "r"(b0), "r"(b1));
}

// ---------------- prepass: permute + cvt weights into fragment order ----------------
__global__ void pack_weights(const float* __restrict__ W1, const float* __restrict__ W2) {
    int i = blockIdx.x * 256 + threadIdx.x;
    const float* src;
    uint32_t* dst;
    int k, n;
    if (i < 384 * 128) {
        k = i >> 7; n = i & 127; src = W1; dst = g_W1p;
    } else {
        int i2 = i - 384 * 128;
        if (i2 >= 128 * 128) return;
        k = i2 >> 7; n = i2 & 127; src = W2; dst = g_W2p;
    }
    const int chunk = k >> 5;
    const int kk    = k & 31;
    const int ks    = kk >> 3;
    const int tg    = kk & 3;
    const int p     = (kk >> 2) & 1;
    const int half  = n >> 6;
    const int g     = n & 7;
    const int j     = (n & 63) >> 3;
    const int dest  = chunk * B_CHUNK_FL +
                      ((ks * 2 + half) * 4 + tg) * 132 + g * 16 + j * 2 + p;
    dst[dest] = f2tf(src[(size_t)k * 128 + n]);
}

// ---------------- main kernel ----------------
__global__ __launch_bounds__(THREADS, 2)
void edge_block_mma(const float* __restrict__ node_attr,
                    const float* __restrict__ edge_attr,
                    const int*   __restrict__ senders,
                    const int*   __restrict__ receivers,
                    const float* __restrict__ b1,
                    const float* __restrict__ b2,
                    const float* __restrict__ ln_g,
                    const float* __restrict__ ln_b,
                    float* __restrict__ out,
                    int E)
{
    extern __shared__ float smem[];
    float* prm = smem + OFF_PRM;
    float* ps  = smem + OFF_PS;

    const uint32_t sbase = smem_u32(smem);

    const int tid  = threadIdx.x;
    const int lane = tid & 31;
    const int wid  = tid >> 5;
    const int g    = lane >> 2;
    const int tig  = lane & 3;
    const int wm   = (wid >> 1) * 32;
    const int wn   = (wid & 1) * 64;
    const int wc   = wid & 1;
    const int rot  = wid & 3;          // ks phase stagger per warp
    const int eb   = blockIdx.x * CTA_M;

    if (tid < 128) {
        prm[tid]       = b1[tid];
        prm[128 + tid] = b2[tid];
        prm[256 + tid] = ln_g[tid];
        prm[384 + tid] = ln_b[tid];
    }

    const int arow  = tid >> 1;
    const int ahalf = tid & 1;
    int eg = eb + arow;
    if (eg >= E) eg = E - 1;
    const int sidx = senders[eg];
    const int ridx = receivers[eg];
    const float* base_s = node_attr + (size_t)sidx * 128;
    const float* base_r = node_attr + (size_t)ridx * 128;
    const float* base_e = edge_attr + (size_t)eg  * 128;

    const uint32_t offA[2] = {
        sbase + (OFF_A0 + arow * A_STR + ahalf * 16) * 4u,
        sbase + (OFF_A1 + arow * A_STR + ahalf * 16) * 4u };
    const uint32_t offB[2] = { sbase + OFF_B0 * 4u, sbase + OFF_B1 * 4u };

    auto copy_bchunk = [&](const uint32_t* gsrc, int buf) {
        const uint32_t dstb = offB[buf];
        #pragma unroll
        for (int r = 0; r < 4; ++r)
            cp16(dstb + (tid + 256 * r) * 16u, gsrc + (tid + 256 * r) * 4);
        if (tid < 32)
            cp16(dstb + (1024 + tid) * 16u, gsrc + (1024 + tid) * 4);
    };

    auto issue_chunk1 = [&](int ch) {
        const int buf = ch & 1;
        const int sel = ch >> 2;
        const float* ab = (sel == 0) ? base_s : ((sel == 1) ? base_r : base_e);
        const float* asrc = ab + (ch & 3) * 32 + ahalf * 16;
        #pragma unroll
        for (int i = 0; i < 4; ++i)
            cp16(offA[buf] + i * 16, asrc + i * 4);
        copy_bchunk(g_W1p + (size_t)ch * B_CHUNK_FL, buf);
    };
    auto issue_w2 = [&](int ch) {
        copy_bchunk(g_W2p + (size_t)ch * B_CHUNK_FL, ch & 1);
    };

    float acc[2][8][4];
    #pragma unroll
    for (int i = 0; i < 2; ++i)
        #pragma unroll
        for (int j = 0; j < 8; ++j)
            #pragma unroll
            for (int c = 0; c < 4; ++c) acc[i][j][c] = 0.f;

    issue_chunk1(0);
    CP_COMMIT();

    const int halfsel = wn >> 6;

    // ======================= GEMM1: 12 chunks of k=32 =======================
    #pragma unroll 1
    for (int ch = 0; ch < 12; ++ch) {
        CP_WAIT0();
        __syncthreads();
        if (ch < 11) { issue_chunk1(ch + 1); CP_COMMIT(); }
        else         { issue_w2(0);          CP_COMMIT(); }   // buf0 free (ch10 done)

        const float* Af = smem + (ch & 1 ? OFF_A1 : OFF_A0) + (wm + g) * A_STR;
        const uint4* Bq = reinterpret_cast<const uint4*>(
                              smem + (ch & 1 ? OFF_B1 : OFF_B0));

        float ar[2][8];
        {
            const int ka0 = rot * 8 + tig;
            #pragma unroll
            for (int i = 0; i < 2; ++i) {
                ar[0][i*4+0] = Af[(16*i)     * A_STR + ka0];
                ar[0][i*4+1] = Af[(16*i + 8) * A_STR + ka0];
                ar[0][i*4+2] = Af[(16*i)     * A_STR + ka0 + 4];
                ar[0][i*4+3] = Af[(16*i + 8) * A_STR + ka0 + 4];
            }
        }
        #pragma unroll
        for (int s = 0; s < 4; ++s) {
            const int ks  = (s + rot) & 3;
            const int cur = s & 1, nxt = cur ^ 1;
            const uint4* bp = Bq + (size_t)((ks * 2 + halfsel) * 4 + tig) * 33 + g * 4;
            uint4 r0 = bp[0], r1 = bp[1], r2 = bp[2], r3 = bp[3];
            if (s < 3) {
                const int kan = (((s + 1) + rot) & 3) * 8 + tig;
                #pragma unroll
                for (int i = 0; i < 2; ++i) {
                    ar[nxt][i*4+0] = Af[(16*i)     * A_STR + kan];
                    ar[nxt][i*4+1] = Af[(16*i + 8) * A_STR + kan];
                    ar[nxt][i*4+2] = Af[(16*i)     * A_STR + kan + 4];
                    ar[nxt][i*4+3] = Af[(16*i + 8) * A_STR + kan + 4];
                }
            }
            uint32_t av[2][4];
            #pragma unroll
            for (int i = 0; i < 2; ++i) {
                av[i][0] = f2tf(ar[cur][i*4+0]);
                av[i][1] = f2tf(ar[cur][i*4+1]);
                av[i][2] = f2tf(ar[cur][i*4+2]);
                av[i][3] = f2tf(ar[cur][i*4+3]);
            }
            #pragma unroll
            for (int i = 0; i < 2; ++i) {
                mma8(acc[i][0], av[i][0], av[i][1], av[i][2], av[i][3], r0.x, r0.y);
                mma8(acc[i][1], av[i][0], av[i][1], av[i][2], av[i][3], r0.z, r0.w);
                mma8(acc[i][2], av[i][0], av[i][1], av[i][2], av[i][3], r1.x, r1.y);
                mma8(acc[i][3], av[i][0], av[i][1], av[i][2], av[i][3], r1.z, r1.w);
                mma8(acc[i][4], av[i][0], av[i][1], av[i][2], av[i][3], r2.x, r2.y);
                mma8(acc[i][5], av[i][0], av[i][1], av[i][2], av[i][3], r2.z, r2.w);
                mma8(acc[i][6], av[i][0], av[i][1], av[i][2], av[i][3], r3.x, r3.y);
                mma8(acc[i][7], av[i][0], av[i][1], av[i][2], av[i][3], r3.z, r3.w);
            }
        }
    }
    __syncthreads();   // GEMM1 reads done; A region free for H

    // ---- H = relu(acc + b1) -> H[m][k] tf32 (STS.64 pairs); W2(0) already in flight
    {
        uint32_t* Hsu = reinterpret_cast<uint32_t*>(smem + OFF_H);
        float b1v[8][2];
        #pragma unroll
        for (int j = 0; j < 8; ++j) {
            b1v[j][0] = prm[wn + 8 * j + 2 * tig];
            b1v[j][1] = prm[wn + 8 * j + 2 * tig + 1];
        }
        #pragma unroll
        for (int i = 0; i < 2; ++i) {
            const int r0 = wm + 16 * i + g;
            #pragma unroll
            for (int j = 0; j < 8; ++j) {
                const int n0 = wn + 8 * j + 2 * tig;
                uint2 h01 = make_uint2(f2tf(fmaxf(acc[i][j][0] + b1v[j][0], 0.f)),
                                       f2tf(fmaxf(acc[i][j][1] + b1v[j][1], 0.f)));
                uint2 h23 = make_uint2(f2tf(fmaxf(acc[i][j][2] + b1v[j][0], 0.f)),
                                       f2tf(fmaxf(acc[i][j][3] + b1v[j][1], 0.f)));
                *reinterpret_cast<uint2*>(&Hsu[r0 * H_STR + n0])       = h01;
                *reinterpret_cast<uint2*>(&Hsu[(r0 + 8) * H_STR + n0]) = h23;
            }
        }
    }

    #pragma unroll
    for (int i = 0; i < 2; ++i)
        #pragma unroll
        for (int j = 0; j < 8; ++j)
            #pragma unroll
            for (int c = 0; c < 4; ++c) acc[i][j][c] = 0.f;

    // ======================= GEMM2: 4 chunks of k=32 =======================
    #pragma unroll 1
    for (int ch = 0; ch < 4; ++ch) {
        CP_WAIT0();
        __syncthreads();
        if (ch < 3) { issue_w2(ch + 1); CP_COMMIT(); }

        const uint32_t* Hf = reinterpret_cast<const uint32_t*>(smem + OFF_H)
                             + (wm + g) * H_STR + ch * 32;
        const uint4* Bq = reinterpret_cast<const uint4*>(
                              smem + (ch & 1 ? OFF_B1 : OFF_B0));

        uint32_t hr[2][8];
        {
            const int ka0 = rot * 8 + tig;
            #pragma unroll
            for (int i = 0; i < 2; ++i) {
                hr[0][i*4+0] = Hf[(16*i)     * H_STR + ka0];
                hr[0][i*4+1] = Hf[(16*i + 8) * H_STR + ka0];
                hr[0][i*4+2] = Hf[(16*i)     * H_STR + ka0 + 4];
                hr[0][i*4+3] = Hf[(16*i + 8) * H_STR + ka0 + 4];
            }
        }
        #pragma unroll
        for (int s = 0; s < 4; ++s) {
            const int ks  = (s + rot) & 3;
            const int cur = s & 1, nxt = cur ^ 1;
            const uint4* bp = Bq + (size_t)((ks * 2 + halfsel) * 4 + tig) * 33 + g * 4;
            uint4 r0 = bp[0], r1 = bp[1], r2 = bp[2], r3 = bp[3];
            if (s < 3) {
                const int kan = (((s + 1) + rot) & 3) * 8 + tig;
                #pragma unroll
                for (int i = 0; i < 2; ++i) {
                    hr[nxt][i*4+0] = Hf[(16*i)     * H_STR + kan];
                    hr[nxt][i*4+1] = Hf[(16*i + 8) * H_STR + kan];
                    hr[nxt][i*4+2] = Hf[(16*i)     * H_STR + kan + 4];
                    hr[nxt][i*4+3] = Hf[(16*i + 8) * H_STR + kan + 4];
                }
            }
            #pragma unroll
            for (int i = 0; i < 2; ++i) {
                mma8(acc[i][0], hr[cur][i*4+0], hr[cur][i*4+1], hr[cur][i*4+2], hr[cur][i*4+3], r0.x, r0.y);
                mma8(acc[i][1], hr[cur][i*4+0], hr[cur][i*4+1], hr[cur][i*4+2], hr[cur][i*4+3], r0.z, r0.w);
                mma8(acc[i][2], hr[cur][i*4+0], hr[cur][i*4+1], hr[cur][i*4+2], hr[cur][i*4+3], r1.x, r1.y);
                mma8(acc[i][3], hr[cur][i*4+0], hr[cur][i*4+1], hr[cur][i*4+2], hr[cur][i*4+3], r1.z, r1.w);
                mma8(acc[i][4], hr[cur][i*4+0], hr[cur][i*4+1], hr[cur][i*4+2], hr[cur][i*4+3], r2.x, r2.y);
                mma8(acc[i][5], hr[cur][i*4+0], hr[cur][i*4+1], hr[cur][i*4+2], hr[cur][i*4+3], r2.z, r2.w);
                mma8(acc[i][6], hr[cur][i*4+0], hr[cur][i*4+1], hr[cur][i*4+2], hr[cur][i*4+3], r3.x, r3.y);
                mma8(acc[i][7], hr[cur][i*4+0], hr[cur][i*4+1], hr[cur][i*4+2], hr[cur][i*4+3], r3.z, r3.w);
            }
        }
    }

    // ======================= LayerNorm epilogue =======================
    float b2v[8][2], gv[8][2], bev[8][2];
    #pragma unroll
    for (int j = 0; j < 8; ++j) {
        const int n0 = wn + 8 * j + 2 * tig;
        b2v[j][0] = prm[128 + n0]; b2v[j][1] = prm[128 + n0 + 1];
        gv[j][0]  = prm[256 + n0]; gv[j][1]  = prm[256 + n0 + 1];
        bev[j][0] = prm[384 + n0]; bev[j][1] = prm[384 + n0 + 1];
    }

    #pragma unroll
    for (int i = 0; i < 2; ++i) {
        float s0 = 0.f, q0 = 0.f, s1 = 0.f, q1 = 0.f;
        #pragma unroll
        for (int j = 0; j < 8; ++j) {
            float v0 = acc[i][j][0] + b2v[j][0];
            float v1 = acc[i][j][1] + b2v[j][1];
            float v2 = acc[i][j][2] + b2v[j][0];
            float v3 = acc[i][j][3] + b2v[j][1];
            acc[i][j][0] = v0; acc[i][j][1] = v1; acc[i][j][2] = v2; acc[i][j][3] = v3;
            s0 += v0 + v1; q0 += v0 * v0 + v1 * v1;
            s1 += v2 + v3; q1 += v2 * v2 + v3 * v3;
        }
        #pragma unroll
        for (int m = 1; m < 4; m <<= 1) {
            s0 += __shfl_xor_sync(0xffffffffu, s0, m);
            q0 += __shfl_xor_sync(0xffffffffu, q0, m);
            s1 += __shfl_xor_sync(0xffffffffu, s1, m);
            q1 += __shfl_xor_sync(0xffffffffu, q1, m);
        }
        if (tig == 0) {
            const int r0 = wm + 16 * i + g;
            ps[wc * 128 + r0]           = s0;
            ps[wc * 128 + r0 + 8]       = s1;
            ps[256 + wc * 128 + r0]     = q0;
            ps[256 + wc * 128 + r0 + 8] = q1;
        }
    }
    __syncthreads();

    #pragma unroll
    for (int i = 0; i < 2; ++i) {
        const int r0 = wm + 16 * i + g;
        const int r1 = r0 + 8;
        float s0 = ps[r0] + ps[128 + r0];
        float q0 = ps[256 + r0] + ps[384 + r0];
        float s1 = ps[r1] + ps[128 + r1];
        float q1 = ps[256 + r1] + ps[384 + r1];
        const float mu0 = s0 * (1.f / 128.f);
        const float mu1 = s1 * (1.f / 128.f);
        const float rs0 = rsqrtf(q0 * (1.f / 128.f) - mu0 * mu0 + 1e-5f);
        const float rs1 = rsqrtf(q1 * (1.f / 128.f) - mu1 * mu1 + 1e-5f);
        const int eg0 = eb + r0;
        const int eg1 = eb + r1;
        if (eg0 < E) {
            float* orow = out + (size_t)eg0 * 128;
            #pragma unroll
            for (int j = 0; j < 8; ++j) {
                const int n0 = wn + 8 * j + 2 * tig;
                float o0 = (acc[i][j][0] - mu0) * rs0 * gv[j][0] + bev[j][0];
                float o1 = (acc[i][j][1] - mu0) * rs0 * gv[j][1] + bev[j][1];
                *reinterpret_cast<float2*>(orow + n0) = make_float2(o0, o1);
            }
        }
        if (eg1 < E) {
            float* orow = out + (size_t)eg1 * 128;
            #pragma unroll
            for (int j = 0; j < 8; ++j) {
                const int n0 = wn + 8 * j + 2 * tig;
                float o2 = (acc[i][j][2] - mu1) * rs1 * gv[j][0] + bev[j][0];
                float o3 = (acc[i][j][3] - mu1) * rs1 * gv[j][1] + bev[j][1];
                *reinterpret_cast<float2*>(orow + n0) = make_float2(o2, o3);
            }
        }
    }
}

extern "C" void kernel_launch(void* const* d_in, const int* in_sizes, int n_in,
                              void* d_out, int out_size)
{
    (void)n_in; (void)out_size;
    const float* node_attr = (const float*)d_in[0];
    const float* edge_attr = (const float*)d_in[1];
    const int*   senders   = (const int*)  d_in[2];
    const int*   receivers = (const int*)  d_in[3];
    const float* W1        = (const float*)d_in[4];
    const float* b1        = (const float*)d_in[5];
    const float* W2        = (const float*)d_in[6];
    const float* b2        = (const float*)d_in[7];
    const float* ln_gamma  = (const float*)d_in[8];
    const float* ln_beta   = (const float*)d_in[9];
    float* out = (float*)d_out;

    const int E = in_sizes[2];

    pack_weights<<<256, 256>>>(W1, W2);

    cudaFuncSetAttribute(edge_block_mma,
                         cudaFuncAttributeMaxDynamicSharedMemorySize, SMEM_BYTES);

    const int grid = (E + CTA_M - 1) / CTA_M;
    edge_block_mma<<<grid, THREADS, SMEM_BYTES>>>(
        node_attr, edge_attr, senders, receivers,
        b1, b2, ln_gamma, ln_beta, out, E);
}